// round 2
// baseline (speedup 1.0000x reference)
#include <cuda_runtime.h>
#include <cuda_bf16.h>

// ---------------------------------------------------------------------------
// GAT 3-layer + PairNorm. N=50000 nodes, E=800000 edges (+N self loops).
// Strategy:
//   - Build CSR-by-dst once per call (int atomics only).
//   - Per layer: tiled FP32 GEMM -> attention coefs -> warp-per-node
//     softmax-aggregation (NO float atomics) -> fused pairnorm+relu.
//   - Layer 3 fuses head-mean + bias, writes d_out directly.
// ---------------------------------------------------------------------------

#define MAXN 50000
#define MAXE 1000000   // E + N with margin

__device__ __align__(16) float g_xh[MAXN * 128];
__device__ __align__(16) float g_agg[MAXN * 128];
__device__ __align__(16) float g_h[MAXN * 128];
__device__ __align__(16) float g_als[MAXN * 2];
__device__ __align__(16) float g_ald[MAXN * 2];
__device__ __align__(16) float g_colsum[128];
__device__ int g_cnt[MAXN + 1];
__device__ int g_off[MAXN + 1];
__device__ int g_cur[MAXN];
__device__ int g_csr[MAXE];
__device__ int g_is64;

// ---------------------------------------------------------------------------
// edge_index dtype probe: JAX int64 may have been silently downcast to int32.
// If all of the first 32 int64 interpretations are in [0,N), it's int64.
// ---------------------------------------------------------------------------
__global__ void detect_kernel(const void* ei, int N) {
    const long long* p = (const long long*)ei;
    long long v = p[threadIdx.x];
    int ok = (v >= 0 && v < (long long)N);
    unsigned b = __ballot_sync(0xffffffffu, ok);
    if (threadIdx.x == 0) g_is64 = (b == 0xffffffffu) ? 1 : 0;
}

__device__ __forceinline__ int edge_val(const void* ei, int idx) {
    if (g_is64) return (int)((const long long*)ei)[idx];
    return ((const int*)ei)[idx];
}

__global__ void zero_int_kernel(int* p, int n) {
    int i = blockIdx.x * blockDim.x + threadIdx.x;
    if (i < n) p[i] = 0;
}
__global__ void zero_f_kernel(float* p, int n) {
    int i = blockIdx.x * blockDim.x + threadIdx.x;
    if (i < n) p[i] = 0.f;
}

__global__ void hist_kernel(const void* ei, int E, int Etot, int* cnt) {
    int e = blockIdx.x * blockDim.x + threadIdx.x;
    if (e >= Etot) return;
    int dst = (e < E) ? edge_val(ei, E + e) : (e - E);
    atomicAdd(&cnt[dst], 1);
}

// single-block exclusive scan over n counts -> off[0..n], cursor copy
__global__ void scan_kernel(const int* cnt, int* off, int* cur, int n) {
    __shared__ int sm[1024];
    int t = threadIdx.x;
    int CH = (n + 1023) >> 10;
    int base = t * CH;
    int s = 0;
    for (int i = 0; i < CH; i++) {
        int idx = base + i;
        if (idx < n) s += cnt[idx];
    }
    sm[t] = s;
    __syncthreads();
    for (int d = 1; d < 1024; d <<= 1) {
        int v = (t >= d) ? sm[t - d] : 0;
        __syncthreads();
        sm[t] += v;
        __syncthreads();
    }
    int run = sm[t] - s;   // exclusive prefix of this thread's chunk
    for (int i = 0; i < CH; i++) {
        int idx = base + i;
        if (idx < n) {
            off[idx] = run;
            cur[idx] = run;
            run += cnt[idx];
        }
    }
    if (t == 1023) off[n] = run;
}

__global__ void scatter_kernel(const void* ei, int E, int Etot, int* cur, int* csr) {
    int e = blockIdx.x * blockDim.x + threadIdx.x;
    if (e >= Etot) return;
    int src, dst;
    if (e < E) { src = edge_val(ei, e); dst = edge_val(ei, E + e); }
    else       { src = dst = e - E; }
    int pos = atomicAdd(&cur[dst], 1);
    csr[pos] = src;
}

// ---------------------------------------------------------------------------
// GEMM: C[N x OW] = A[N x 128] * W[128 x OW], tiled, 256 threads / block.
// ---------------------------------------------------------------------------
template <int OW>
__global__ void gemm_kernel(const float* __restrict__ A, const float* __restrict__ W,
                            float* __restrict__ C, int N) {
    constexpr int BK = 32;
    constexpr int BM = 64;
    constexpr int CT = OW / 8;        // threads along cols
    constexpr int RT = 256 / CT;      // threads along rows
    constexpr int RPT = BM / RT;      // rows per thread
    __shared__ float As[BM][BK + 1];
    __shared__ float Ws[BK][OW];
    int t = threadIdx.x;
    int tx = t % CT, ty = t / CT;
    int row0 = blockIdx.x * BM;
    float acc[RPT][8];
#pragma unroll
    for (int r = 0; r < RPT; r++)
#pragma unroll
        for (int j = 0; j < 8; j++) acc[r][j] = 0.f;

    for (int k0 = 0; k0 < 128; k0 += BK) {
        for (int i = t; i < BM * BK; i += 256) {
            int r = i / BK, c = i % BK;
            int gr = row0 + r;
            As[r][c] = (gr < N) ? A[gr * 128 + k0 + c] : 0.f;
        }
        for (int i = t; i < BK * OW; i += 256) {
            int r = i / OW, c = i % OW;
            Ws[r][c] = W[(k0 + r) * OW + c];
        }
        __syncthreads();
#pragma unroll
        for (int kk = 0; kk < BK; kk++) {
            float wv[8];
#pragma unroll
            for (int j = 0; j < 8; j++) wv[j] = Ws[kk][tx * 8 + j];
#pragma unroll
            for (int r = 0; r < RPT; r++) {
                float av = As[ty * RPT + r][kk];
#pragma unroll
                for (int j = 0; j < 8; j++) acc[r][j] = fmaf(av, wv[j], acc[r][j]);
            }
        }
        __syncthreads();
    }
    for (int r = 0; r < RPT; r++) {
        int gr = row0 + ty * RPT + r;
        if (gr < N) {
#pragma unroll
            for (int j = 0; j < 8; j++) C[gr * OW + tx * 8 + j] = acc[r][j];
        }
    }
}

// ---------------------------------------------------------------------------
// attention coefs: al_s[n,h] = dot(xh[n,h,:], a_src[h,:]); same for al_d.
// warp per node; lane l owns features l*4..l*4+3; a[h*D+d] indexes same as feat.
// ---------------------------------------------------------------------------
template <int HD>
__global__ void attn_kernel(const float* __restrict__ xh,
                            const float* __restrict__ asrc, const float* __restrict__ adst,
                            float* __restrict__ als, float* __restrict__ ald, int N) {
    constexpr int D = HD / 2;
    constexpr int L = HD / 4;
    constexpr int SEG = D / 4;  // lanes per head
    int wid = (blockIdx.x * blockDim.x + threadIdx.x) >> 5;
    int lane = threadIdx.x & 31;
    if (wid >= N) return;
    float ps = 0.f, pd = 0.f;
    if (lane < L) {
        float4 v = ((const float4*)xh)[(size_t)wid * L + lane];
        float4 a = ((const float4*)asrc)[lane];
        float4 b = ((const float4*)adst)[lane];
        ps = v.x * a.x + v.y * a.y + v.z * a.z + v.w * a.w;
        pd = v.x * b.x + v.y * b.y + v.z * b.z + v.w * b.w;
    }
#pragma unroll
    for (int o = SEG / 2; o > 0; o >>= 1) {
        ps += __shfl_down_sync(0xffffffffu, ps, o, SEG);
        pd += __shfl_down_sync(0xffffffffu, pd, o, SEG);
    }
    if (lane < L && (lane % SEG) == 0) {
        int h = lane / SEG;
        als[wid * 2 + h] = ps;
        ald[wid * 2 + h] = pd;
    }
}

__device__ __forceinline__ float lrelu(float x) { return fmaxf(x, 0.2f * x); }

// ---------------------------------------------------------------------------
// Softmax aggregation: warp (or sub-warp) per destination node. No atomics.
// pass1: max of logits over in-edges. pass2: acc += exp(l-m)*xh[src], s += exp.
// ---------------------------------------------------------------------------
template <int HD, bool FINAL>
__global__ void aggr_kernel(const float* __restrict__ xh,
                            const float* __restrict__ als, const float* __restrict__ ald,
                            const int* __restrict__ off, const int* __restrict__ csr,
                            const float* __restrict__ bias,
                            float* __restrict__ out, int N) {
    constexpr int D = HD / 2;
    constexpr int L = HD / 4;          // lanes per node (32 or 8)
    constexpr int NPW = 32 / L;        // nodes per warp (1 or 4)
    int wid = (blockIdx.x * blockDim.x + threadIdx.x) >> 5;
    int lane = threadIdx.x & 31;
    if (wid * NPW >= N) return;        // N % NPW == 0 -> uniform exit
    int sub = lane / L;
    int lig = lane % L;
    int n = wid * NPW + sub;

    float2 ad = ((const float2*)ald)[n];
    int st = off[n], en = off[n + 1];

    // pass 1: per-head max over in-edges (split over group lanes)
    float m0 = -1e30f, m1 = -1e30f;
    for (int i = st + lig; i < en; i += L) {
        int s = csr[i];
        float2 as = ((const float2*)als)[s];
        m0 = fmaxf(m0, lrelu(as.x + ad.x));
        m1 = fmaxf(m1, lrelu(as.y + ad.y));
    }
#pragma unroll
    for (int o = L / 2; o > 0; o >>= 1) {
        m0 = fmaxf(m0, __shfl_xor_sync(0xffffffffu, m0, o));
        m1 = fmaxf(m1, __shfl_xor_sync(0xffffffffu, m1, o));
    }

    // pass 2: weighted accumulation (all lanes recompute w; loads broadcast)
    int head = (lig * 4) / D;
    float s0 = 0.f, s1 = 0.f;
    float4 acc = make_float4(0.f, 0.f, 0.f, 0.f);
    const float4* x4 = (const float4*)xh;
    for (int i = st; i < en; i++) {
        int s = csr[i];
        float2 as = ((const float2*)als)[s];
        float w0 = __expf(lrelu(as.x + ad.x) - m0);
        float w1 = __expf(lrelu(as.y + ad.y) - m1);
        s0 += w0; s1 += w1;
        float w = head ? w1 : w0;
        float4 v = x4[(size_t)s * L + lig];
        acc.x = fmaf(w, v.x, acc.x);
        acc.y = fmaf(w, v.y, acc.y);
        acc.z = fmaf(w, v.z, acc.z);
        acc.w = fmaf(w, v.w, acc.w);
    }
    float inv = 1.0f / (head ? s1 : s0);
    acc.x *= inv; acc.y *= inv; acc.z *= inv; acc.w *= inv;

    if (FINAL) {
        // HD=32: lanes lig<4 hold head0 feats, lig>=4 head1. mean + bias.
        float ox = __shfl_down_sync(0xffffffffu, acc.x, 4);
        float oy = __shfl_down_sync(0xffffffffu, acc.y, 4);
        float oz = __shfl_down_sync(0xffffffffu, acc.z, 4);
        float ow = __shfl_down_sync(0xffffffffu, acc.w, 4);
        if (lig < 4) {
            float4 r;
            r.x = 0.5f * (acc.x + ox) + bias[lig * 4 + 0];
            r.y = 0.5f * (acc.y + oy) + bias[lig * 4 + 1];
            r.z = 0.5f * (acc.z + oz) + bias[lig * 4 + 2];
            r.w = 0.5f * (acc.w + ow) + bias[lig * 4 + 3];
            ((float4*)out)[(size_t)n * 4 + lig] = r;
        }
    } else {
        ((float4*)out)[(size_t)n * L + lig] = acc;
    }
}

// ---------------------------------------------------------------------------
// PairNorm + ReLU
// ---------------------------------------------------------------------------
__global__ void colsum_kernel(const float* __restrict__ in, float* __restrict__ cs, int N) {
    float s = 0.f;
    int c = threadIdx.x;  // 128 threads
    for (int r = blockIdx.x; r < N; r += gridDim.x) s += in[(size_t)r * 128 + c];
    atomicAdd(&cs[c], s);
}

__global__ void pairnorm_kernel(const float* __restrict__ in, const float* __restrict__ cs,
                                float* __restrict__ out, int N) {
    int wid = (blockIdx.x * blockDim.x + threadIdx.x) >> 5;
    int lane = threadIdx.x & 31;
    if (wid >= N) return;
    float invN = 1.0f / (float)N;
    float4 m = ((const float4*)cs)[lane];
    float4 v = ((const float4*)in)[(size_t)wid * 32 + lane];
    v.x -= m.x * invN; v.y -= m.y * invN; v.z -= m.z * invN; v.w -= m.w * invN;
    float n2 = v.x * v.x + v.y * v.y + v.z * v.z + v.w * v.w;
#pragma unroll
    for (int o = 16; o > 0; o >>= 1) n2 += __shfl_xor_sync(0xffffffffu, n2, o);
    float sc = 1.0f / (1e-5f + sqrtf(n2));
    float4 r;
    r.x = fmaxf(v.x * sc, 0.f);
    r.y = fmaxf(v.y * sc, 0.f);
    r.z = fmaxf(v.z * sc, 0.f);
    r.w = fmaxf(v.w * sc, 0.f);
    ((float4*)out)[(size_t)wid * 32 + lane] = r;
}

// ---------------------------------------------------------------------------
extern "C" void kernel_launch(void* const* d_in, const int* in_sizes, int n_in,
                              void* d_out, int out_size) {
    const float* x   = (const float*)d_in[0];
    const void*  ei  = d_in[1];
    const float* W1  = (const float*)d_in[2];
    const float* as1 = (const float*)d_in[3];
    const float* ad1 = (const float*)d_in[4];
    const float* W2  = (const float*)d_in[6];
    const float* as2 = (const float*)d_in[7];
    const float* ad2 = (const float*)d_in[8];
    const float* W3  = (const float*)d_in[10];
    const float* as3 = (const float*)d_in[11];
    const float* ad3 = (const float*)d_in[12];
    const float* b3  = (const float*)d_in[13];

    int N = in_sizes[0] / 128;
    int E = in_sizes[1] / 2;
    int Etot = E + N;

    float *xh, *agg, *h, *als, *ald, *cs;
    int *cnt, *off, *cur, *csr;
    cudaGetSymbolAddress((void**)&xh, g_xh);
    cudaGetSymbolAddress((void**)&agg, g_agg);
    cudaGetSymbolAddress((void**)&h, g_h);
    cudaGetSymbolAddress((void**)&als, g_als);
    cudaGetSymbolAddress((void**)&ald, g_ald);
    cudaGetSymbolAddress((void**)&cs, g_colsum);
    cudaGetSymbolAddress((void**)&cnt, g_cnt);
    cudaGetSymbolAddress((void**)&off, g_off);
    cudaGetSymbolAddress((void**)&cur, g_cur);
    cudaGetSymbolAddress((void**)&csr, g_csr);

    const int TB = 256;
    int ewarp_blocks  = (N + 7) / 8;        // warp-per-node kernels, 8 warps/blk
    int ewarp_blocks4 = (N / 4 + 7) / 8;    // 4 nodes/warp kernels
    int gemm_blocks   = (N + 63) / 64;

    // ---- CSR build (shared by all 3 layers) ----
    detect_kernel<<<1, 32>>>(ei, N);
    zero_int_kernel<<<(N + TB - 1) / TB, TB>>>(cnt, N);
    hist_kernel<<<(Etot + TB - 1) / TB, TB>>>(ei, E, Etot, cnt);
    scan_kernel<<<1, 1024>>>(cnt, off, cur, N);
    scatter_kernel<<<(Etot + TB - 1) / TB, TB>>>(ei, E, Etot, cur, csr);

    // ---- layer 1 ----
    gemm_kernel<128><<<gemm_blocks, TB>>>(x, W1, xh, N);
    attn_kernel<128><<<ewarp_blocks, TB>>>(xh, as1, ad1, als, ald, N);
    aggr_kernel<128, false><<<ewarp_blocks, TB>>>(xh, als, ald, off, csr, nullptr, agg, N);
    zero_f_kernel<<<1, 128>>>(cs, 128);
    colsum_kernel<<<512, 128>>>(agg, cs, N);
    pairnorm_kernel<<<ewarp_blocks, TB>>>(agg, cs, h, N);

    // ---- layer 2 ----
    gemm_kernel<128><<<gemm_blocks, TB>>>(h, W2, xh, N);
    attn_kernel<128><<<ewarp_blocks, TB>>>(xh, as2, ad2, als, ald, N);
    aggr_kernel<128, false><<<ewarp_blocks, TB>>>(xh, als, ald, off, csr, nullptr, agg, N);
    zero_f_kernel<<<1, 128>>>(cs, 128);
    colsum_kernel<<<512, 128>>>(agg, cs, N);
    pairnorm_kernel<<<ewarp_blocks, TB>>>(agg, cs, h, N);

    // ---- layer 3 (writes d_out with head-mean + bias) ----
    gemm_kernel<32><<<gemm_blocks, TB>>>(h, W3, xh, N);
    attn_kernel<32><<<ewarp_blocks, TB>>>(xh, as3, ad3, als, ald, N);
    aggr_kernel<32, true><<<ewarp_blocks4, TB>>>(xh, als, ald, off, csr, b3, (float*)d_out, N);
}

// round 3
// speedup vs baseline: 1.2063x; 1.2063x over previous
#include <cuda_runtime.h>
#include <cuda_bf16.h>

// ---------------------------------------------------------------------------
// GAT 3-layer + PairNorm. N=50000 nodes, E=800000 edges (+N self loops).
//   - CSR-by-dst built per call (int atomics + decoupled 3-kernel scan).
//   - Per layer: tiled FP32 GEMM with fused attention-coef epilogue ->
//     single-pass (no-max) softmax aggregation, warp-per-node, no float
//     atomics -> fused pairnorm+relu.
//   - Layer 3 fuses head-mean + bias, writes d_out directly.
// ---------------------------------------------------------------------------

#define MAXN 50000
#define MAXE 1000000   // E + N with margin

__device__ __align__(16) float g_xh[MAXN * 128];
__device__ __align__(16) float g_agg[MAXN * 128];
__device__ __align__(16) float g_h[MAXN * 128];
__device__ __align__(16) float g_als[MAXN * 2];
__device__ __align__(16) float g_ald[MAXN * 2];
__device__ __align__(16) float g_colsum[128];
__device__ int g_cnt[MAXN + 1];
__device__ int g_off[MAXN + 1];
__device__ int g_cur[MAXN];
__device__ int g_csr[MAXE];
__device__ int g_bsum[256];
__device__ int g_bpre[256];
__device__ int g_is64;

// ---------------------------------------------------------------------------
// edge_index dtype probe: JAX int64 may have been silently downcast to int32.
// ---------------------------------------------------------------------------
__global__ void detect_kernel(const void* ei, int N) {
    const long long* p = (const long long*)ei;
    long long v = p[threadIdx.x];
    int ok = (v >= 0 && v < (long long)N);
    unsigned b = __ballot_sync(0xffffffffu, ok);
    if (threadIdx.x == 0) g_is64 = (b == 0xffffffffu) ? 1 : 0;
}

__device__ __forceinline__ int edge_val(const void* ei, int idx) {
    if (g_is64) return (int)((const long long*)ei)[idx];
    return ((const int*)ei)[idx];
}

__global__ void zero_int_kernel(int* p, int n) {
    int i = blockIdx.x * blockDim.x + threadIdx.x;
    if (i < n) p[i] = 0;
}
__global__ void zero_f_kernel(float* p, int n) {
    int i = blockIdx.x * blockDim.x + threadIdx.x;
    if (i < n) p[i] = 0.f;
}

__global__ void hist_kernel(const void* ei, int E, int Etot, int* cnt) {
    int e = blockIdx.x * blockDim.x + threadIdx.x;
    if (e >= Etot) return;
    int dst = (e < E) ? edge_val(ei, E + e) : (e - E);
    atomicAdd(&cnt[dst], 1);
}

// ---------------------------------------------------------------------------
// Decoupled scan: k1 per-block sums, k2 scan of block sums (<=256 blocks of
// 256), k3 per-block exclusive scan + offset write.
// ---------------------------------------------------------------------------
__global__ void scan_bsum_kernel(const int* __restrict__ cnt, int* __restrict__ bsum, int n) {
    int t = threadIdx.x;
    int i = blockIdx.x * 256 + t;
    int v = (i < n) ? cnt[i] : 0;
#pragma unroll
    for (int o = 16; o > 0; o >>= 1) v += __shfl_down_sync(0xffffffffu, v, o);
    __shared__ int ws[8];
    if ((t & 31) == 0) ws[t >> 5] = v;
    __syncthreads();
    if (t == 0) {
        int s = 0;
#pragma unroll
        for (int w = 0; w < 8; w++) s += ws[w];
        bsum[blockIdx.x] = s;
    }
}

__global__ void scan_bscan_kernel(const int* __restrict__ bsum, int* __restrict__ bpre,
                                  int* __restrict__ off, int nb, int n) {
    __shared__ int sm[256];
    int t = threadIdx.x;
    int v = (t < nb) ? bsum[t] : 0;
    sm[t] = v;
    __syncthreads();
#pragma unroll
    for (int d = 1; d < 256; d <<= 1) {
        int x = (t >= d) ? sm[t - d] : 0;
        __syncthreads();
        sm[t] += x;
        __syncthreads();
    }
    if (t < nb) bpre[t] = sm[t] - v;
    if (t == 255) off[n] = sm[255];
}

__global__ void scan_write_kernel(const int* __restrict__ cnt, const int* __restrict__ bpre,
                                  int* __restrict__ off, int* __restrict__ cur, int n) {
    __shared__ int sm[256];
    int t = threadIdx.x;
    int i = blockIdx.x * 256 + t;
    int v = (i < n) ? cnt[i] : 0;
    sm[t] = v;
    __syncthreads();
#pragma unroll
    for (int d = 1; d < 256; d <<= 1) {
        int x = (t >= d) ? sm[t - d] : 0;
        __syncthreads();
        sm[t] += x;
        __syncthreads();
    }
    if (i < n) {
        int o = bpre[blockIdx.x] + sm[t] - v;
        off[i] = o;
        cur[i] = o;
    }
}

__global__ void scatter_kernel(const void* ei, int E, int Etot, int* cur, int* csr) {
    int e = blockIdx.x * blockDim.x + threadIdx.x;
    if (e >= Etot) return;
    int src, dst;
    if (e < E) { src = edge_val(ei, e); dst = edge_val(ei, E + e); }
    else       { src = dst = e - E; }
    int pos = atomicAdd(&cur[dst], 1);
    csr[pos] = src;
}

// ---------------------------------------------------------------------------
// GEMM: C[N x OW] = A[N x 128] * W[128 x OW], fused attention-coef epilogue:
// als[n,h] = dot(C[n, h*D:(h+1)*D], asrc[h*D:(h+1)*D]); same for ald.
// ---------------------------------------------------------------------------
template <int OW>
__global__ void gemm_attn_kernel(const float* __restrict__ A, const float* __restrict__ W,
                                 const float* __restrict__ asrc, const float* __restrict__ adst,
                                 float* __restrict__ C,
                                 float* __restrict__ als, float* __restrict__ ald, int N) {
    constexpr int BK = 32;
    constexpr int BM = 64;
    constexpr int CT = OW / 8;        // threads along cols
    constexpr int RT = 256 / CT;      // threads along rows
    constexpr int RPT = BM / RT;      // rows per thread
    constexpr int TPH = CT / 2;       // threads per head (per row)
    __shared__ float As[BM][BK + 1];
    __shared__ float Ws[BK][OW];
    __shared__ float Ps[BM][CT];      // partial src dots
    __shared__ float Pd[BM][CT];      // partial dst dots
    int t = threadIdx.x;
    int tx = t % CT, ty = t / CT;
    int row0 = blockIdx.x * BM;
    float acc[RPT][8];
#pragma unroll
    for (int r = 0; r < RPT; r++)
#pragma unroll
        for (int j = 0; j < 8; j++) acc[r][j] = 0.f;

    for (int k0 = 0; k0 < 128; k0 += BK) {
        for (int i = t; i < BM * BK; i += 256) {
            int r = i / BK, c = i % BK;
            int gr = row0 + r;
            As[r][c] = (gr < N) ? A[gr * 128 + k0 + c] : 0.f;
        }
        for (int i = t; i < BK * OW; i += 256) {
            int r = i / OW, c = i % OW;
            Ws[r][c] = W[(k0 + r) * OW + c];
        }
        __syncthreads();
#pragma unroll
        for (int kk = 0; kk < BK; kk++) {
            float wv[8];
#pragma unroll
            for (int j = 0; j < 8; j++) wv[j] = Ws[kk][tx * 8 + j];
#pragma unroll
            for (int r = 0; r < RPT; r++) {
                float av = As[ty * RPT + r][kk];
#pragma unroll
                for (int j = 0; j < 8; j++) acc[r][j] = fmaf(av, wv[j], acc[r][j]);
            }
        }
        __syncthreads();
    }

    // attention partials: thread covers cols [tx*8, tx*8+8), all one head.
    float av[8], bv[8];
#pragma unroll
    for (int j = 0; j < 8; j++) { av[j] = asrc[tx * 8 + j]; bv[j] = adst[tx * 8 + j]; }

#pragma unroll
    for (int r = 0; r < RPT; r++) {
        int row = ty * RPT + r;
        int gr = row0 + row;
        float s = 0.f, d = 0.f;
#pragma unroll
        for (int j = 0; j < 8; j++) {
            s = fmaf(acc[r][j], av[j], s);
            d = fmaf(acc[r][j], bv[j], d);
        }
        Ps[row][tx] = s;
        Pd[row][tx] = d;
        if (gr < N) {
#pragma unroll
            for (int j = 0; j < 8; j++) C[gr * OW + tx * 8 + j] = acc[r][j];
        }
    }
    __syncthreads();
    // 128 tasks: (row, head)
    if (t < BM * 2) {
        int row = t >> 1, h = t & 1;
        int gr = row0 + row;
        if (gr < N) {
            float s = 0.f, d = 0.f;
#pragma unroll
            for (int k = 0; k < TPH; k++) {
                s += Ps[row][h * TPH + k];
                d += Pd[row][h * TPH + k];
            }
            als[gr * 2 + h] = s;
            ald[gr * 2 + h] = d;
        }
    }
}

__device__ __forceinline__ float lrelu(float x) { return fmaxf(x, 0.2f * x); }

// ---------------------------------------------------------------------------
// Single-pass softmax aggregation (logits bounded -> no max subtraction).
// Warp (or sub-warp) per destination node. No float atomics.
// ---------------------------------------------------------------------------
template <int HD, bool FINAL>
__global__ void aggr_kernel(const float* __restrict__ xh,
                            const float* __restrict__ als, const float* __restrict__ ald,
                            const int* __restrict__ off, const int* __restrict__ csr,
                            const float* __restrict__ bias,
                            float* __restrict__ out, int N) {
    constexpr int D = HD / 2;
    constexpr int L = HD / 4;          // lanes per node (32 or 8)
    constexpr int NPW = 32 / L;        // nodes per warp (1 or 4)
    int wid = (blockIdx.x * blockDim.x + threadIdx.x) >> 5;
    int lane = threadIdx.x & 31;
    if (wid * NPW >= N) return;
    int lig = lane % L;
    int n = wid * NPW + lane / L;

    float2 ad = ((const float2*)ald)[n];
    int st = off[n], en = off[n + 1];

    int head = (lig * 4) / D;
    float s0 = 0.f, s1 = 0.f;
    float4 acc = make_float4(0.f, 0.f, 0.f, 0.f);
    const float4* x4 = (const float4*)xh;
#pragma unroll 4
    for (int i = st; i < en; i++) {
        int s = csr[i];
        float2 as = ((const float2*)als)[s];
        float w0 = __expf(lrelu(as.x + ad.x));
        float w1 = __expf(lrelu(as.y + ad.y));
        s0 += w0; s1 += w1;
        float w = head ? w1 : w0;
        float4 v = x4[(size_t)s * L + lig];
        acc.x = fmaf(w, v.x, acc.x);
        acc.y = fmaf(w, v.y, acc.y);
        acc.z = fmaf(w, v.z, acc.z);
        acc.w = fmaf(w, v.w, acc.w);
    }
    float inv = 1.0f / (head ? s1 : s0);
    acc.x *= inv; acc.y *= inv; acc.z *= inv; acc.w *= inv;

    if (FINAL) {
        // HD=32: lanes lig<4 hold head0 feats, lig>=4 head1. mean + bias.
        float ox = __shfl_down_sync(0xffffffffu, acc.x, 4);
        float oy = __shfl_down_sync(0xffffffffu, acc.y, 4);
        float oz = __shfl_down_sync(0xffffffffu, acc.z, 4);
        float ow = __shfl_down_sync(0xffffffffu, acc.w, 4);
        if (lig < 4) {
            float4 r;
            r.x = 0.5f * (acc.x + ox) + bias[lig * 4 + 0];
            r.y = 0.5f * (acc.y + oy) + bias[lig * 4 + 1];
            r.z = 0.5f * (acc.z + oz) + bias[lig * 4 + 2];
            r.w = 0.5f * (acc.w + ow) + bias[lig * 4 + 3];
            ((float4*)out)[(size_t)n * 4 + lig] = r;
        }
    } else {
        ((float4*)out)[(size_t)n * L + lig] = acc;
    }
}

// ---------------------------------------------------------------------------
// PairNorm + ReLU
// ---------------------------------------------------------------------------
__global__ void colsum_kernel(const float* __restrict__ in, float* __restrict__ cs, int N) {
    float s = 0.f;
    int c = threadIdx.x;  // 128 threads
    for (int r = blockIdx.x; r < N; r += gridDim.x) s += in[(size_t)r * 128 + c];
    atomicAdd(&cs[c], s);
}

__global__ void pairnorm_kernel(const float* __restrict__ in, const float* __restrict__ cs,
                                float* __restrict__ out, int N) {
    int wid = (blockIdx.x * blockDim.x + threadIdx.x) >> 5;
    int lane = threadIdx.x & 31;
    if (wid >= N) return;
    float invN = 1.0f / (float)N;
    float4 m = ((const float4*)cs)[lane];
    float4 v = ((const float4*)in)[(size_t)wid * 32 + lane];
    v.x -= m.x * invN; v.y -= m.y * invN; v.z -= m.z * invN; v.w -= m.w * invN;
    float n2 = v.x * v.x + v.y * v.y + v.z * v.z + v.w * v.w;
#pragma unroll
    for (int o = 16; o > 0; o >>= 1) n2 += __shfl_xor_sync(0xffffffffu, n2, o);
    float sc = 1.0f / (1e-5f + sqrtf(n2));
    float4 r;
    r.x = fmaxf(v.x * sc, 0.f);
    r.y = fmaxf(v.y * sc, 0.f);
    r.z = fmaxf(v.z * sc, 0.f);
    r.w = fmaxf(v.w * sc, 0.f);
    ((float4*)out)[(size_t)wid * 32 + lane] = r;
}

// ---------------------------------------------------------------------------
extern "C" void kernel_launch(void* const* d_in, const int* in_sizes, int n_in,
                              void* d_out, int out_size) {
    const float* x   = (const float*)d_in[0];
    const void*  ei  = d_in[1];
    const float* W1  = (const float*)d_in[2];
    const float* as1 = (const float*)d_in[3];
    const float* ad1 = (const float*)d_in[4];
    const float* W2  = (const float*)d_in[6];
    const float* as2 = (const float*)d_in[7];
    const float* ad2 = (const float*)d_in[8];
    const float* W3  = (const float*)d_in[10];
    const float* as3 = (const float*)d_in[11];
    const float* ad3 = (const float*)d_in[12];
    const float* b3  = (const float*)d_in[13];

    int N = in_sizes[0] / 128;
    int E = in_sizes[1] / 2;
    int Etot = E + N;

    float *xh, *agg, *h, *als, *ald, *cs;
    int *cnt, *off, *cur, *csr, *bsum, *bpre;
    cudaGetSymbolAddress((void**)&xh, g_xh);
    cudaGetSymbolAddress((void**)&agg, g_agg);
    cudaGetSymbolAddress((void**)&h, g_h);
    cudaGetSymbolAddress((void**)&als, g_als);
    cudaGetSymbolAddress((void**)&ald, g_ald);
    cudaGetSymbolAddress((void**)&cs, g_colsum);
    cudaGetSymbolAddress((void**)&cnt, g_cnt);
    cudaGetSymbolAddress((void**)&off, g_off);
    cudaGetSymbolAddress((void**)&cur, g_cur);
    cudaGetSymbolAddress((void**)&csr, g_csr);
    cudaGetSymbolAddress((void**)&bsum, g_bsum);
    cudaGetSymbolAddress((void**)&bpre, g_bpre);

    const int TB = 256;
    int ewarp_blocks  = (N + 7) / 8;        // warp-per-node kernels, 8 warps/blk
    int ewarp_blocks4 = (N / 4 + 7) / 8;    // 4 nodes/warp kernels
    int gemm_blocks   = (N + 63) / 64;
    int nb1 = (N + 255) / 256;              // scan block count (<=256 required)

    // ---- CSR build (shared by all 3 layers) ----
    detect_kernel<<<1, 32>>>(ei, N);
    zero_int_kernel<<<(N + TB - 1) / TB, TB>>>(cnt, N);
    hist_kernel<<<(Etot + TB - 1) / TB, TB>>>(ei, E, Etot, cnt);
    scan_bsum_kernel<<<nb1, 256>>>(cnt, bsum, N);
    scan_bscan_kernel<<<1, 256>>>(bsum, bpre, off, nb1, N);
    scan_write_kernel<<<nb1, 256>>>(cnt, bpre, off, cur, N);
    scatter_kernel<<<(Etot + TB - 1) / TB, TB>>>(ei, E, Etot, cur, csr);

    // ---- layer 1 ----
    gemm_attn_kernel<128><<<gemm_blocks, TB>>>(x, W1, as1, ad1, xh, als, ald, N);
    aggr_kernel<128, false><<<ewarp_blocks, TB>>>(xh, als, ald, off, csr, nullptr, agg, N);
    zero_f_kernel<<<1, 128>>>(cs, 128);
    colsum_kernel<<<512, 128>>>(agg, cs, N);
    pairnorm_kernel<<<ewarp_blocks, TB>>>(agg, cs, h, N);

    // ---- layer 2 ----
    gemm_attn_kernel<128><<<gemm_blocks, TB>>>(h, W2, as2, ad2, xh, als, ald, N);
    aggr_kernel<128, false><<<ewarp_blocks, TB>>>(xh, als, ald, off, csr, nullptr, agg, N);
    zero_f_kernel<<<1, 128>>>(cs, 128);
    colsum_kernel<<<512, 128>>>(agg, cs, N);
    pairnorm_kernel<<<ewarp_blocks, TB>>>(agg, cs, h, N);

    // ---- layer 3 (writes d_out with head-mean + bias) ----
    gemm_attn_kernel<32><<<gemm_blocks, TB>>>(h, W3, as3, ad3, xh, als, ald, N);
    aggr_kernel<32, true><<<ewarp_blocks4, TB>>>(xh, als, ald, off, csr, b3, (float*)d_out, N);
}

// round 4
// speedup vs baseline: 1.7043x; 1.4129x over previous
#include <cuda_runtime.h>
#include <cuda_bf16.h>

// ---------------------------------------------------------------------------
// GAT 3-layer + PairNorm. N=50000 nodes, E=800000 edges (+N self loops).
//   - CSR-by-dst built per call (int atomics + decoupled 3-kernel scan).
//   - Per layer: tiled FP32 GEMM (f32x2 packed FMA) with fused attention-coef
//     epilogue -> single-pass softmax aggregation (warp-per-node, no float
//     atomics) with fused column-sum -> fused pairnorm+relu.
//   - Layer 3 fuses head-mean + bias, writes d_out directly.
// ---------------------------------------------------------------------------

#define MAXN 50000
#define MAXE 1000000   // E + N with margin

__device__ __align__(16) float g_xh[MAXN * 128];
__device__ __align__(16) float g_agg[MAXN * 128];
__device__ __align__(16) float g_h[MAXN * 128];
__device__ __align__(16) float g_als[MAXN * 2];
__device__ __align__(16) float g_ald[MAXN * 2];
__device__ __align__(16) float g_colsum[128];
__device__ int g_cnt[MAXN + 1];
__device__ int g_off[MAXN + 1];
__device__ int g_cur[MAXN];
__device__ int g_csr[MAXE];
__device__ int g_bsum[256];
__device__ int g_bpre[256];
__device__ int g_is64;

// ---------------------------------------------------------------------------
// edge_index dtype probe: JAX int64 may have been silently downcast to int32.
// ---------------------------------------------------------------------------
__global__ void detect_kernel(const void* ei, int N) {
    const long long* p = (const long long*)ei;
    long long v = p[threadIdx.x];
    int ok = (v >= 0 && v < (long long)N);
    unsigned b = __ballot_sync(0xffffffffu, ok);
    if (threadIdx.x == 0) g_is64 = (b == 0xffffffffu) ? 1 : 0;
}

__device__ __forceinline__ int edge_val(const void* ei, int idx) {
    if (g_is64) return (int)((const long long*)ei)[idx];
    return ((const int*)ei)[idx];
}

__global__ void zero_int_kernel(int* p, int n) {
    int i = blockIdx.x * blockDim.x + threadIdx.x;
    if (i < n) p[i] = 0;
}

__global__ void hist_kernel(const void* ei, int E, int Etot, int* cnt) {
    int e = blockIdx.x * blockDim.x + threadIdx.x;
    if (e >= Etot) return;
    int dst = (e < E) ? edge_val(ei, E + e) : (e - E);
    atomicAdd(&cnt[dst], 1);
}

// ---------------------------------------------------------------------------
// Decoupled scan
// ---------------------------------------------------------------------------
__global__ void scan_bsum_kernel(const int* __restrict__ cnt, int* __restrict__ bsum, int n) {
    int t = threadIdx.x;
    int i = blockIdx.x * 256 + t;
    int v = (i < n) ? cnt[i] : 0;
#pragma unroll
    for (int o = 16; o > 0; o >>= 1) v += __shfl_down_sync(0xffffffffu, v, o);
    __shared__ int ws[8];
    if ((t & 31) == 0) ws[t >> 5] = v;
    __syncthreads();
    if (t == 0) {
        int s = 0;
#pragma unroll
        for (int w = 0; w < 8; w++) s += ws[w];
        bsum[blockIdx.x] = s;
    }
}

__global__ void scan_bscan_kernel(const int* __restrict__ bsum, int* __restrict__ bpre,
                                  int* __restrict__ off, int nb, int n) {
    __shared__ int sm[256];
    int t = threadIdx.x;
    int v = (t < nb) ? bsum[t] : 0;
    sm[t] = v;
    __syncthreads();
#pragma unroll
    for (int d = 1; d < 256; d <<= 1) {
        int x = (t >= d) ? sm[t - d] : 0;
        __syncthreads();
        sm[t] += x;
        __syncthreads();
    }
    if (t < nb) bpre[t] = sm[t] - v;
    if (t == 255) off[n] = sm[255];
}

__global__ void scan_write_kernel(const int* __restrict__ cnt, const int* __restrict__ bpre,
                                  int* __restrict__ off, int* __restrict__ cur, int n) {
    __shared__ int sm[256];
    int t = threadIdx.x;
    int i = blockIdx.x * 256 + t;
    int v = (i < n) ? cnt[i] : 0;
    sm[t] = v;
    __syncthreads();
#pragma unroll
    for (int d = 1; d < 256; d <<= 1) {
        int x = (t >= d) ? sm[t - d] : 0;
        __syncthreads();
        sm[t] += x;
        __syncthreads();
    }
    if (i < n) {
        int o = bpre[blockIdx.x] + sm[t] - v;
        off[i] = o;
        cur[i] = o;
    }
}

__global__ void scatter_kernel(const void* ei, int E, int Etot, int* cur, int* csr) {
    int e = blockIdx.x * blockDim.x + threadIdx.x;
    if (e >= Etot) return;
    int src, dst;
    if (e < E) { src = edge_val(ei, e); dst = edge_val(ei, E + e); }
    else       { src = dst = e - E; }
    int pos = atomicAdd(&cur[dst], 1);
    csr[pos] = src;
}

// ---------------------------------------------------------------------------
// GEMM: C[N x OW] = A[N x 128] * W[128 x OW], f32x2 packed FMA inner loop.
// Thread (tx,ty) owns column PAIRS (2tx, 2tx+1) + j*2*CT, j=0..3 (8 cols).
// Pairs j=0,1 are head 0; j=2,3 head 1 (since 2*CT*2 == OW/2).
// Fused epilogue: als/ald per (row, head). Optionally zeroes cs_zero[0:128).
// ---------------------------------------------------------------------------
template <int OW>
__global__ void __launch_bounds__(256)
gemm_attn_kernel(const float* __restrict__ A, const float* __restrict__ W,
                 const float* __restrict__ asrc, const float* __restrict__ adst,
                 float* __restrict__ C,
                 float* __restrict__ als, float* __restrict__ ald,
                 float* __restrict__ cs_zero, int N) {
    constexpr int BK = 32;
    constexpr int BM = 64;
    constexpr int CT = OW / 8;        // threads along cols
    constexpr int RT = 256 / CT;      // threads along rows
    constexpr int RPT = BM / RT;      // rows per thread
    __shared__ float As[BM][BK + 1];
    __shared__ float Ws[BK][OW];
    __shared__ float Ps0[BM][CT], Pd0[BM][CT];   // head-0 partial dots
    __shared__ float Ps1[BM][CT], Pd1[BM][CT];   // head-1 partial dots
    int t = threadIdx.x;
    int tx = t % CT, ty = t / CT;
    int row0 = blockIdx.x * BM;

    if (cs_zero && blockIdx.x == 0 && t < 128) cs_zero[t] = 0.f;

    unsigned long long acc2[RPT][4];
#pragma unroll
    for (int r = 0; r < RPT; r++)
#pragma unroll
        for (int j = 0; j < 4; j++) acc2[r][j] = 0ULL;

    for (int k0 = 0; k0 < 128; k0 += BK) {
        for (int i = t; i < BM * BK; i += 256) {
            int r = i / BK, c = i % BK;
            int gr = row0 + r;
            As[r][c] = (gr < N) ? A[gr * 128 + k0 + c] : 0.f;
        }
        for (int i = t; i < BK * OW; i += 256) {
            int r = i / OW, c = i % OW;
            Ws[r][c] = W[(k0 + r) * OW + c];
        }
        __syncthreads();
#pragma unroll
        for (int kk = 0; kk < BK; kk++) {
            unsigned long long wv2[4];
#pragma unroll
            for (int j = 0; j < 4; j++)
                wv2[j] = *(const unsigned long long*)&Ws[kk][2 * tx + j * 2 * CT];
#pragma unroll
            for (int r = 0; r < RPT; r++) {
                float av = As[ty * RPT + r][kk];
                unsigned long long av2;
                asm("mov.b64 %0, {%1, %1};" : "=l"(av2) : "f"(av));
#pragma unroll
                for (int j = 0; j < 4; j++)
                    asm("fma.rn.f32x2 %0, %1, %2, %0;" : "+l"(acc2[r][j]) : "l"(av2), "l"(wv2[j]));
            }
        }
        __syncthreads();
    }

    // attention vectors for this thread's column pairs
    float2 av[4], bv[4];
#pragma unroll
    for (int j = 0; j < 4; j++) {
        av[j] = ((const float2*)asrc)[tx + j * CT];
        bv[j] = ((const float2*)adst)[tx + j * CT];
    }

#pragma unroll
    for (int r = 0; r < RPT; r++) {
        int row = ty * RPT + r;
        int gr = row0 + row;
        float s0 = 0.f, d0 = 0.f, s1 = 0.f, d1 = 0.f;
        float2 c2[4];
#pragma unroll
        for (int j = 0; j < 4; j++) {
            float lo, hi;
            asm("mov.b64 {%0, %1}, %2;" : "=f"(lo), "=f"(hi) : "l"(acc2[r][j]));
            c2[j] = make_float2(lo, hi);
            if (j < 2) {
                s0 = fmaf(lo, av[j].x, fmaf(hi, av[j].y, s0));
                d0 = fmaf(lo, bv[j].x, fmaf(hi, bv[j].y, d0));
            } else {
                s1 = fmaf(lo, av[j].x, fmaf(hi, av[j].y, s1));
                d1 = fmaf(lo, bv[j].x, fmaf(hi, bv[j].y, d1));
            }
        }
        Ps0[row][tx] = s0; Pd0[row][tx] = d0;
        Ps1[row][tx] = s1; Pd1[row][tx] = d1;
        if (gr < N) {
#pragma unroll
            for (int j = 0; j < 4; j++)
                ((float2*)&C[(size_t)gr * OW])[tx + j * CT] = c2[j];
        }
    }
    __syncthreads();
    // 128 tasks: (row, head)
    if (t < BM * 2) {
        int row = t >> 1, h = t & 1;
        int gr = row0 + row;
        if (gr < N) {
            float s = 0.f, d = 0.f;
#pragma unroll
            for (int k = 0; k < CT; k++) {
                s += h ? Ps1[row][k] : Ps0[row][k];
                d += h ? Pd1[row][k] : Pd0[row][k];
            }
            als[gr * 2 + h] = s;
            ald[gr * 2 + h] = d;
        }
    }
}

__device__ __forceinline__ float lrelu(float x) { return fmaxf(x, 0.2f * x); }

// ---------------------------------------------------------------------------
// Single-pass softmax aggregation (logits bounded -> no max subtraction).
// Warp (or sub-warp) per destination node. No float atomics for features;
// fused column-sum via per-block smem staging + 128 REDG adds.
// ---------------------------------------------------------------------------
template <int HD, bool FINAL>
__global__ void __launch_bounds__(256)
aggr_kernel(const float* __restrict__ xh,
            const float* __restrict__ als, const float* __restrict__ ald,
            const int* __restrict__ off, const int* __restrict__ csr,
            const float* __restrict__ bias,
            float* __restrict__ out, float* __restrict__ cs, int N) {
    constexpr int D = HD / 2;
    constexpr int L = HD / 4;          // lanes per node (32 or 8)
    constexpr int NPW = 32 / L;        // nodes per warp (1 or 4)
    int wib = threadIdx.x >> 5;
    int wid = blockIdx.x * 8 + wib;
    int lane = threadIdx.x & 31;
    int lig = lane % L;
    int nreq = wid * NPW + lane / L;
    bool valid = nreq < N;
    int n = valid ? nreq : (N - 1);

    float2 ad = ((const float2*)ald)[n];
    int st = off[n], en = off[n + 1];

    int head = (lig * 4) / D;
    float s0 = 0.f, s1 = 0.f;
    float4 acc = make_float4(0.f, 0.f, 0.f, 0.f);
    const float4* x4 = (const float4*)xh;
#pragma unroll 4
    for (int i = st; i < en; i++) {
        int s = csr[i];
        float2 as = ((const float2*)als)[s];
        float w0 = __expf(lrelu(as.x + ad.x));
        float w1 = __expf(lrelu(as.y + ad.y));
        s0 += w0; s1 += w1;
        float w = head ? w1 : w0;
        float4 v = x4[(size_t)s * L + lig];
        acc.x = fmaf(w, v.x, acc.x);
        acc.y = fmaf(w, v.y, acc.y);
        acc.z = fmaf(w, v.z, acc.z);
        acc.w = fmaf(w, v.w, acc.w);
    }
    float inv = 1.0f / (head ? s1 : s0);
    acc.x *= inv; acc.y *= inv; acc.z *= inv; acc.w *= inv;

    if (FINAL) {
        // HD=32: lanes lig<4 hold head0 feats, lig>=4 head1. mean + bias.
        float ox = __shfl_down_sync(0xffffffffu, acc.x, 4);
        float oy = __shfl_down_sync(0xffffffffu, acc.y, 4);
        float oz = __shfl_down_sync(0xffffffffu, acc.z, 4);
        float ow = __shfl_down_sync(0xffffffffu, acc.w, 4);
        if (valid && lig < 4) {
            float4 r;
            r.x = 0.5f * (acc.x + ox) + bias[lig * 4 + 0];
            r.y = 0.5f * (acc.y + oy) + bias[lig * 4 + 1];
            r.z = 0.5f * (acc.z + oz) + bias[lig * 4 + 2];
            r.w = 0.5f * (acc.w + ow) + bias[lig * 4 + 3];
            ((float4*)out)[(size_t)n * 4 + lig] = r;
        }
    } else {
        if (valid) ((float4*)out)[(size_t)n * L + lig] = acc;
        // fused column-sum: stage 8 node rows, reduce, one REDG per column
        __shared__ float csm[8][128];
        float4 a = valid ? acc : make_float4(0.f, 0.f, 0.f, 0.f);
        ((float4*)csm[wib])[lig] = a;
        __syncthreads();
        int t = threadIdx.x;
        if (t < 128) {
            float s = 0.f;
#pragma unroll
            for (int w = 0; w < 8; w++) s += csm[w][t];
            atomicAdd(&cs[t], s);
        }
    }
}

// ---------------------------------------------------------------------------
// PairNorm + ReLU
// ---------------------------------------------------------------------------
__global__ void pairnorm_kernel(const float* __restrict__ in, const float* __restrict__ cs,
                                float* __restrict__ out, int N) {
    int wid = (blockIdx.x * blockDim.x + threadIdx.x) >> 5;
    int lane = threadIdx.x & 31;
    if (wid >= N) return;
    float invN = 1.0f / (float)N;
    float4 m = ((const float4*)cs)[lane];
    float4 v = ((const float4*)in)[(size_t)wid * 32 + lane];
    v.x -= m.x * invN; v.y -= m.y * invN; v.z -= m.z * invN; v.w -= m.w * invN;
    float n2 = v.x * v.x + v.y * v.y + v.z * v.z + v.w * v.w;
#pragma unroll
    for (int o = 16; o > 0; o >>= 1) n2 += __shfl_xor_sync(0xffffffffu, n2, o);
    float sc = 1.0f / (1e-5f + sqrtf(n2));
    float4 r;
    r.x = fmaxf(v.x * sc, 0.f);
    r.y = fmaxf(v.y * sc, 0.f);
    r.z = fmaxf(v.z * sc, 0.f);
    r.w = fmaxf(v.w * sc, 0.f);
    ((float4*)out)[(size_t)wid * 32 + lane] = r;
}

// ---------------------------------------------------------------------------
extern "C" void kernel_launch(void* const* d_in, const int* in_sizes, int n_in,
                              void* d_out, int out_size) {
    const float* x   = (const float*)d_in[0];
    const void*  ei  = d_in[1];
    const float* W1  = (const float*)d_in[2];
    const float* as1 = (const float*)d_in[3];
    const float* ad1 = (const float*)d_in[4];
    const float* W2  = (const float*)d_in[6];
    const float* as2 = (const float*)d_in[7];
    const float* ad2 = (const float*)d_in[8];
    const float* W3  = (const float*)d_in[10];
    const float* as3 = (const float*)d_in[11];
    const float* ad3 = (const float*)d_in[12];
    const float* b3  = (const float*)d_in[13];

    int N = in_sizes[0] / 128;
    int E = in_sizes[1] / 2;
    int Etot = E + N;

    float *xh, *agg, *h, *als, *ald, *cs;
    int *cnt, *off, *cur, *csr, *bsum, *bpre;
    cudaGetSymbolAddress((void**)&xh, g_xh);
    cudaGetSymbolAddress((void**)&agg, g_agg);
    cudaGetSymbolAddress((void**)&h, g_h);
    cudaGetSymbolAddress((void**)&als, g_als);
    cudaGetSymbolAddress((void**)&ald, g_ald);
    cudaGetSymbolAddress((void**)&cs, g_colsum);
    cudaGetSymbolAddress((void**)&cnt, g_cnt);
    cudaGetSymbolAddress((void**)&off, g_off);
    cudaGetSymbolAddress((void**)&cur, g_cur);
    cudaGetSymbolAddress((void**)&csr, g_csr);
    cudaGetSymbolAddress((void**)&bsum, g_bsum);
    cudaGetSymbolAddress((void**)&bpre, g_bpre);

    const int TB = 256;
    int ewarp_blocks  = (N + 7) / 8;        // warp-per-node kernels, 8 warps/blk
    int ewarp_blocks4 = (N / 4 + 7) / 8;    // 4 nodes/warp kernels
    int gemm_blocks   = (N + 63) / 64;
    int nb1 = (N + 255) / 256;              // scan block count (<=256 required)

    // ---- CSR build (shared by all 3 layers) ----
    detect_kernel<<<1, 32>>>(ei, N);
    zero_int_kernel<<<(N + TB - 1) / TB, TB>>>(cnt, N);
    hist_kernel<<<(Etot + TB - 1) / TB, TB>>>(ei, E, Etot, cnt);
    scan_bsum_kernel<<<nb1, 256>>>(cnt, bsum, N);
    scan_bscan_kernel<<<1, 256>>>(bsum, bpre, off, nb1, N);
    scan_write_kernel<<<nb1, 256>>>(cnt, bpre, off, cur, N);
    scatter_kernel<<<(Etot + TB - 1) / TB, TB>>>(ei, E, Etot, cur, csr);

    // ---- layer 1 ----
    gemm_attn_kernel<128><<<gemm_blocks, TB>>>(x, W1, as1, ad1, xh, als, ald, cs, N);
    aggr_kernel<128, false><<<ewarp_blocks, TB>>>(xh, als, ald, off, csr, nullptr, agg, cs, N);
    pairnorm_kernel<<<ewarp_blocks, TB>>>(agg, cs, h, N);

    // ---- layer 2 ----
    gemm_attn_kernel<128><<<gemm_blocks, TB>>>(h, W2, as2, ad2, xh, als, ald, cs, N);
    aggr_kernel<128, false><<<ewarp_blocks, TB>>>(xh, als, ald, off, csr, nullptr, agg, cs, N);
    pairnorm_kernel<<<ewarp_blocks, TB>>>(agg, cs, h, N);

    // ---- layer 3 (writes d_out with head-mean + bias) ----
    gemm_attn_kernel<32><<<gemm_blocks, TB>>>(h, W3, as3, ad3, xh, als, ald, nullptr, N);
    aggr_kernel<32, true><<<ewarp_blocks4, TB>>>(xh, als, ald, off, csr, b3, (float*)d_out, nullptr, N);
}